// round 1
// baseline (speedup 1.0000x reference)
#include <cuda_runtime.h>
#include <cuda_bf16.h>
#include <math_constants.h>

// Problem constants: x = [B=8, C=256, H=128, W=128] fp32
#define B 8
#define C 256
#define H 128
#define W 128
#define HW (H*W)          // 16384
#define PAD 129           // tile row pitch (conflict-free both directions)

// ---------- scratch (device globals; no runtime allocation) ----------
__device__ float g_u[C];                    // u[c] = sum_o w3[o]*v_w[o,c]
__device__ float g_ub;                      // dot(w3, v_b)
__device__ __align__(16) float g_t3[B*HW];  // u.x + ub  per pixel
__device__ float g_xkpart[B*H*C];           // per-(b,h) partial of sum_n x*exp(klin)
__device__ float g_Zpart[B*H];              // per-(b,h) partial of sum exp(klin)
__device__ float g_cmax[B*H*W];             // max over c at (b,h,w)
__device__ float g_csum[B*H*W];             // sum over c at (b,h,w)
__device__ float g_hmax[B*H];
__device__ float g_hsum[B*H];
__device__ float g_hatt[B*H];
__device__ float g_watt[B*W];
__device__ float g_cf[B*C];                 // channel_fea
__device__ __align__(16) float g_s[B*HW];   // final spatial gate

// ---------- kernel A: precompute u = w3^T v_w, ub = w3.v_b ----------
__global__ void kA(const float* __restrict__ vw, const float* __restrict__ vb,
                   const float* __restrict__ w3) {
    int t = threadIdx.x;
    float u = 0.f;
    #pragma unroll 8
    for (int o = 0; o < C; o++) u = fmaf(w3[o], vw[o*C + t], u);
    g_u[t] = u;
    if (t == 0) {
        float ub = 0.f;
        for (int i = 0; i < C; i++) ub = fmaf(w3[i], vb[i], ub);
        g_ub = ub;
    }
}

// ---------- kernel B: main reduction pass over x ----------
// Block = one (b,h) row: tile of [C=256, W=128] floats held in shared (padded).
// Computes: klin (k_w.x), t3 (u.x), per-w max/sum over c, per-row (h) stats,
// exp(klin) partials for softmax Z, and xk partials = sum_w x[c,w]*exp(klin[w]).
__global__ void __launch_bounds__(256, 1) kB(const float* __restrict__ x,
                                             const float* __restrict__ kw) {
    extern __shared__ float tile[];           // C * PAD floats = 132096 B
    __shared__ float wsh[C], ush[C];
    __shared__ float red[1024];
    __shared__ float esh[W];
    __shared__ float part[12];

    int t = threadIdx.x;
    int h = blockIdx.x, b = blockIdx.y;
    wsh[t] = kw[t];
    ush[t] = g_u[t];
    __syncthreads();

    int w  = t & 127;
    int ch = t >> 7;                          // which half of the channels
    int cbase = ch << 7;
    const float* xp = x + (((size_t)(b*C + cbase)) << 14) + (h << 7) + w;

    float kl = 0.f, t3 = 0.f, mx = -1e30f, sm = 0.f;
    #pragma unroll 8
    for (int j = 0; j < 128; j++) {
        float val = xp[(size_t)j << 14];      // stride H*W between channels
        int c = cbase + j;
        tile[c*PAD + w] = val;
        kl = fmaf(wsh[c], val, kl);
        t3 = fmaf(ush[c], val, t3);
        mx = fmaxf(mx, val);
        sm += val;
    }
    red[t] = kl; red[256 + t] = t3; red[512 + t] = mx; red[768 + t] = sm;
    __syncthreads();

    int bh = (b << 7) + h;
    if (t < 128) {
        float klw = red[t]       + red[128 + t];
        float t3w = red[256 + t] + red[384 + t];
        float mxw = fmaxf(red[512 + t], red[640 + t]);
        float smw = red[768 + t] + red[896 + t];
        float e = __expf(klw);                // klin ~ N(0,1): unshifted exp is safe
        esh[t] = e;
        g_t3[(bh << 7) + t]   = t3w + g_ub;
        g_cmax[(bh << 7) + t] = mxw;
        g_csum[(bh << 7) + t] = smw;
        // warp-level reductions over the 128 w positions (4 active warps)
        float rm = mxw, rs = smw, rz = e;
        #pragma unroll
        for (int o = 16; o; o >>= 1) {
            rm = fmaxf(rm, __shfl_down_sync(0xffffffffu, rm, o));
            rs += __shfl_down_sync(0xffffffffu, rs, o);
            rz += __shfl_down_sync(0xffffffffu, rz, o);
        }
        int wid = t >> 5;
        if ((t & 31) == 0) { part[wid] = rm; part[4 + wid] = rs; part[8 + wid] = rz; }
    }
    __syncthreads();
    if (t == 0) {
        g_hmax[bh]  = fmaxf(fmaxf(part[0], part[1]), fmaxf(part[2], part[3]));
        g_hsum[bh]  = part[4] + part[5] + part[6] + part[7];
        g_Zpart[bh] = part[8] + part[9] + part[10] + part[11];
    }

    // phase 2: xk partial. thread t handles channel c = t.
    // tile reads stride PAD=129 across threads -> conflict-free.
    float acc = 0.f;
    const float* row = tile + t * PAD;
    #pragma unroll 8
    for (int wp = 0; wp < 128; wp++) acc = fmaf(row[wp], esh[wp], acc);
    g_xkpart[(bh << 8) + t] = acc;
}

// ---------- kernel C: per-batch fixups ----------
// Z, xk, channel_fea = v_w @ xk + v_b, h_att, w_att.
__global__ void __launch_bounds__(256) kC(const float* __restrict__ vw,
                                          const float* __restrict__ vb,
                                          const float* __restrict__ w1,
                                          const float* __restrict__ b1,
                                          const float* __restrict__ w2,
                                          const float* __restrict__ b2) {
    __shared__ float xksh[C];
    __shared__ float zp[8];
    __shared__ float zsh;
    int b = blockIdx.x, t = threadIdx.x;

    float z = (t < 128) ? g_Zpart[(b << 7) + t] : 0.f;
    #pragma unroll
    for (int o = 16; o; o >>= 1) z += __shfl_down_sync(0xffffffffu, z, o);
    if ((t & 31) == 0) zp[t >> 5] = z;
    __syncthreads();
    if (t == 0) zsh = zp[0]+zp[1]+zp[2]+zp[3]+zp[4]+zp[5]+zp[6]+zp[7];
    __syncthreads();
    float invZ = 1.f / zsh;

    float acc = 0.f;
    #pragma unroll 4
    for (int hh = 0; hh < 128; hh++) acc += g_xkpart[(((b << 7) + hh) << 8) + t];
    xksh[t] = acc * invZ;
    __syncthreads();

    float cf = vb[t];
    #pragma unroll 8
    for (int c2 = 0; c2 < C; c2++) cf = fmaf(vw[t*C + c2], xksh[c2], cf);
    g_cf[(b << 8) + t] = cf;

    if (t < 128) {
        float ha = fmaf(w1[0], g_hmax[(b << 7) + t],
                   fmaf(w1[1], g_hsum[(b << 7) + t] * (1.f/32768.f), b1[0]));
        g_hatt[(b << 7) + t] = 1.f / (1.f + __expf(-ha));

        float wm = -1e30f, ws = 0.f;
        #pragma unroll 4
        for (int hh = 0; hh < 128; hh++) {
            int idx = (((b << 7) + hh) << 7) + t;
            wm = fmaxf(wm, g_cmax[idx]);
            ws += g_csum[idx];
        }
        float wa = fmaf(w2[0], wm, fmaf(w2[1], ws * (1.f/32768.f), b2[0]));
        g_watt[(b << 7) + t] = 1.f / (1.f + __expf(-wa));
    }
}

// ---------- kernel D: spatial gate s[b,h,w] (only 131072 sigmoids) ----------
__global__ void __launch_bounds__(256) kD(const float* __restrict__ b3) {
    int i = blockIdx.x * 256 + threadIdx.x;    // < B*HW
    int b = i >> 14, n = i & 16383;
    float att = g_hatt[(b << 7) + (n >> 7)] + g_watt[(b << 7) + (n & 127)];
    float zz = fmaf(att, g_t3[i], b3[0]);
    g_s[i] = 1.f / (1.f + __expf(-zz));
}

// ---------- kernel E: streaming output out = s*cf + x ----------
__global__ void __launch_bounds__(256) kE(const float4* __restrict__ x4,
                                          float4* __restrict__ o4) {
    int i = blockIdx.x * 256 + threadIdx.x;    // < B*C*HW/4
    float4 xv = x4[i];
    int b  = i >> 20;
    int c  = (i >> 12) & 255;
    int n4 = i & 4095;
    float4 sv = reinterpret_cast<const float4*>(g_s)[(b << 12) + n4];
    float cf  = g_cf[(b << 8) + c];
    float4 ov;
    ov.x = fmaf(sv.x, cf, xv.x);
    ov.y = fmaf(sv.y, cf, xv.y);
    ov.z = fmaf(sv.z, cf, xv.z);
    ov.w = fmaf(sv.w, cf, xv.w);
    o4[i] = ov;
}

extern "C" void kernel_launch(void* const* d_in, const int* in_sizes, int n_in,
                              void* d_out, int out_size) {
    const float* x  = (const float*)d_in[0];
    const float* vw = (const float*)d_in[1];
    const float* vb = (const float*)d_in[2];
    const float* kw = (const float*)d_in[3];
    // d_in[4] = k_b: softmax is shift-invariant, unused
    const float* w1 = (const float*)d_in[5];
    const float* b1 = (const float*)d_in[6];
    const float* w2 = (const float*)d_in[7];
    const float* b2 = (const float*)d_in[8];
    const float* w3 = (const float*)d_in[9];
    const float* b3 = (const float*)d_in[10];
    float* out = (float*)d_out;

    // 132096 B dynamic smem for kB (idempotent, capture-safe)
    cudaFuncSetAttribute(kB, cudaFuncAttributeMaxDynamicSharedMemorySize, C*PAD*4);

    kA<<<1, 256>>>(vw, vb, w3);
    dim3 gB(H, B);
    kB<<<gB, 256, C*PAD*4>>>(x, kw);
    kC<<<B, 256>>>(vw, vb, w1, b1, w2, b2);
    kD<<<(B*HW)/256, 256>>>(b3);
    kE<<<(B*C*HW/4)/256, 256>>>((const float4*)x, (float4*)out);
}

// round 2
// speedup vs baseline: 1.4764x; 1.4764x over previous
#include <cuda_runtime.h>
#include <cuda_bf16.h>
#include <math_constants.h>

// Problem constants: x = [B=8, C=256, H=128, W=128] fp32
#define B 8
#define C 256
#define H 128
#define W 128
#define HW (H*W)          // 16384
#define WC 64             // w-chunk width per kB block
#define NCH 2             // chunks per row = W/WC
#define TP 65             // tile pitch (odd -> conflict-free both directions)

// ---------- scratch (device globals; no runtime allocation) ----------
__device__ float g_u[C];                        // u[c] = sum_o w3[o]*v_w[o,c]
__device__ float g_ub;                          // dot(w3, v_b)
__device__ __align__(16) float g_t3[B*HW];      // u.x + ub  per pixel
__device__ float g_xkpart[B*H*NCH*C];           // per-(b,h,chunk) partial of sum x*exp(klin)
__device__ float g_Zp[B*H*NCH];                 // partial sum exp(klin)
__device__ float g_cmax[B*H*W];                 // max over c at (b,h,w)
__device__ float g_csum[B*H*W];                 // sum over c at (b,h,w)
__device__ float g_hmaxp[B*H*NCH];
__device__ float g_hsump[B*H*NCH];
__device__ float g_hatt[B*H];
__device__ float g_watt[B*W];
__device__ float g_cf[B*C];                     // channel_fea
__device__ __align__(16) float g_s[B*HW];       // final spatial gate

// ---------- kernel A: u = w3^T v_w (coalesced, 8 blocks), ub = w3.v_b ----------
__global__ void __launch_bounds__(256) kA(const float* __restrict__ vw,
                                          const float* __restrict__ vb,
                                          const float* __restrict__ w3) {
    __shared__ float red[256];
    int t = threadIdx.x, lane = t & 31, g = t >> 5;
    int c = (blockIdx.x << 5) + lane;            // 8 blocks x 32 columns
    float u = 0.f;
    #pragma unroll
    for (int o = g; o < C; o += 8) u = fmaf(w3[o], vw[o*C + c], u);
    red[t] = u;
    __syncthreads();
    if (t < 32) {
        float s = 0.f;
        #pragma unroll
        for (int k2 = 0; k2 < 8; k2++) s += red[(k2 << 5) + t];
        g_u[(blockIdx.x << 5) + t] = s;
    }
    if (blockIdx.x == 0) {
        __syncthreads();                          // protect red reuse
        red[t] = w3[t] * vb[t];
        __syncthreads();
        if (t < 32) {
            float s = 0.f;
            #pragma unroll
            for (int k2 = 0; k2 < 8; k2++) s += red[(k2 << 5) + t];
            #pragma unroll
            for (int o = 16; o; o >>= 1) s += __shfl_down_sync(0xffffffffu, s, o);
            if (t == 0) g_ub = s;
        }
    }
}

// ---------- kernel B: main reduction pass over x ----------
// Block = one (b, h, w-chunk of 64): tile [C=256, 64] in shared (~65KB -> 3 CTA/SM).
// Computes klin, t3, per-w max/sum over c, chunk-level h stats + Z partial,
// and xk partials = sum_w x[c,w]*exp(klin[w]) (unnormalized; Z applied in kC).
__global__ void __launch_bounds__(256) kB(const float* __restrict__ x,
                                          const float* __restrict__ kw) {
    extern __shared__ float tile[];               // C * TP floats = 66560 B
    __shared__ float wsh[C], ush[C];
    __shared__ float red[1024];
    __shared__ float esh[WC];
    __shared__ float part[6];

    int t = threadIdx.x;
    int h = blockIdx.x, chunk = blockIdx.y, b = blockIdx.z;
    wsh[t] = kw[t];
    ush[t] = g_u[t];
    __syncthreads();

    int w = t & 63, g = t >> 6;                   // 4 channel groups of 64
    int w0 = chunk << 6;
    const float* xp = x + (((size_t)(b*C + (g << 6))) << 14) + (h << 7) + w0 + w;

    float kl = 0.f, t3 = 0.f, mx = -1e30f, sm = 0.f;
    #pragma unroll 8
    for (int j = 0; j < 64; j++) {
        float val = xp[(size_t)j << 14];
        int c = (g << 6) + j;
        tile[c*TP + w] = val;
        kl = fmaf(wsh[c], val, kl);
        t3 = fmaf(ush[c], val, t3);
        mx = fmaxf(mx, val);
        sm += val;
    }
    red[t] = kl; red[256 + t] = t3; red[512 + t] = mx; red[768 + t] = sm;
    __syncthreads();

    int bh = (b << 7) + h;
    if (t < 64) {
        float klw = red[t]       + red[64 + t]  + red[128 + t] + red[192 + t];
        float t3w = red[256 + t] + red[320 + t] + red[384 + t] + red[448 + t];
        float mxw = fmaxf(fmaxf(red[512 + t], red[576 + t]),
                          fmaxf(red[640 + t], red[704 + t]));
        float smw = red[768 + t] + red[832 + t] + red[896 + t] + red[960 + t];
        float e = __expf(klw);                    // klin ~ N(0,1): unshifted exp safe
        esh[t] = e;
        int gi = (bh << 7) + w0 + t;
        g_t3[gi]   = t3w + g_ub;
        g_cmax[gi] = mxw;
        g_csum[gi] = smw;
        float rm = mxw, rs = smw, rz = e;
        #pragma unroll
        for (int o = 16; o; o >>= 1) {
            rm = fmaxf(rm, __shfl_down_sync(0xffffffffu, rm, o));
            rs += __shfl_down_sync(0xffffffffu, rs, o);
            rz += __shfl_down_sync(0xffffffffu, rz, o);
        }
        if ((t & 31) == 0) {
            int wi = t >> 5;                      // 0 or 1
            part[wi] = rm; part[2 + wi] = rs; part[4 + wi] = rz;
        }
    }
    __syncthreads();
    int ci = (bh << 1) + chunk;
    if (t == 0) {
        g_hmaxp[ci] = fmaxf(part[0], part[1]);
        g_hsump[ci] = part[2] + part[3];
        g_Zp[ci]    = part[4] + part[5];
    }

    // phase 2: xk partial; thread t = channel c. conflict-free (TP odd).
    float acc = 0.f;
    const float* row = tile + t * TP;
    #pragma unroll
    for (int wp = 0; wp < WC; wp++) acc = fmaf(row[wp], esh[wp], acc);
    g_xkpart[((size_t)ci << 8) + t] = acc;
}

// ---------- kernel C: per-batch fixups ----------
__global__ void __launch_bounds__(256) kC(const float* __restrict__ vw,
                                          const float* __restrict__ vb,
                                          const float* __restrict__ w1,
                                          const float* __restrict__ b1,
                                          const float* __restrict__ w2,
                                          const float* __restrict__ b2) {
    __shared__ float xksh[C];
    __shared__ float zp[8];
    __shared__ float zsh;
    int b = blockIdx.x, t = threadIdx.x;
    int lane = t & 31, wid = t >> 5;

    float z = g_Zp[(b << 8) + t];
    #pragma unroll
    for (int o = 16; o; o >>= 1) z += __shfl_down_sync(0xffffffffu, z, o);
    if (lane == 0) zp[wid] = z;
    __syncthreads();
    if (t == 0) zsh = zp[0]+zp[1]+zp[2]+zp[3]+zp[4]+zp[5]+zp[6]+zp[7];
    __syncthreads();
    float invZ = 1.f / zsh;

    float acc = 0.f;
    #pragma unroll 8
    for (int i = 0; i < 256; i++) acc += g_xkpart[(((size_t)(b << 8) + i) << 8) + t];
    xksh[t] = acc * invZ;
    __syncthreads();

    // cf = v_w @ xk + v_b : warp-per-output-channel, coalesced vw rows
    for (int o = wid; o < C; o += 8) {
        float a = 0.f;
        #pragma unroll
        for (int k2 = 0; k2 < 8; k2++) {
            int c2 = (k2 << 5) + lane;
            a = fmaf(vw[o*C + c2], xksh[c2], a);
        }
        #pragma unroll
        for (int o2 = 16; o2; o2 >>= 1) a += __shfl_down_sync(0xffffffffu, a, o2);
        if (lane == 0) g_cf[(b << 8) + o] = a + vb[o];
    }

    if (t < 128) {
        int i2 = ((b << 7) + t) << 1;
        float hm = fmaxf(g_hmaxp[i2], g_hmaxp[i2 + 1]);
        float hs = g_hsump[i2] + g_hsump[i2 + 1];
        float ha = fmaf(w1[0], hm, fmaf(w1[1], hs * (1.f/32768.f), b1[0]));
        g_hatt[(b << 7) + t] = 1.f / (1.f + __expf(-ha));

        float wm = -1e30f, ws = 0.f;
        #pragma unroll 4
        for (int hh = 0; hh < 128; hh++) {
            int idx = (((b << 7) + hh) << 7) + t;
            wm = fmaxf(wm, g_cmax[idx]);
            ws += g_csum[idx];
        }
        float wa = fmaf(w2[0], wm, fmaf(w2[1], ws * (1.f/32768.f), b2[0]));
        g_watt[(b << 7) + t] = 1.f / (1.f + __expf(-wa));
    }
}

// ---------- kernel D: spatial gate s[b,h,w] ----------
__global__ void __launch_bounds__(256) kD(const float* __restrict__ b3) {
    int i = blockIdx.x * 256 + threadIdx.x;       // < B*HW
    int b = i >> 14, n = i & 16383;
    float att = g_hatt[(b << 7) + (n >> 7)] + g_watt[(b << 7) + (n & 127)];
    float zz = fmaf(att, g_t3[i], b3[0]);
    g_s[i] = 1.f / (1.f + __expf(-zz));
}

// ---------- kernel E: streaming output out = s*cf + x ----------
__global__ void __launch_bounds__(256) kE(const float4* __restrict__ x4,
                                          float4* __restrict__ o4) {
    int i = blockIdx.x * 256 + threadIdx.x;       // < B*C*HW/4
    float4 xv = x4[i];
    int b  = i >> 20;
    int c  = (i >> 12) & 255;
    int n4 = i & 4095;
    float4 sv = reinterpret_cast<const float4*>(g_s)[(b << 12) + n4];
    float cf  = g_cf[(b << 8) + c];
    float4 ov;
    ov.x = fmaf(sv.x, cf, xv.x);
    ov.y = fmaf(sv.y, cf, xv.y);
    ov.z = fmaf(sv.z, cf, xv.z);
    ov.w = fmaf(sv.w, cf, xv.w);
    o4[i] = ov;
}

extern "C" void kernel_launch(void* const* d_in, const int* in_sizes, int n_in,
                              void* d_out, int out_size) {
    const float* x  = (const float*)d_in[0];
    const float* vw = (const float*)d_in[1];
    const float* vb = (const float*)d_in[2];
    const float* kw = (const float*)d_in[3];
    // d_in[4] = k_b: softmax is shift-invariant, unused
    const float* w1 = (const float*)d_in[5];
    const float* b1 = (const float*)d_in[6];
    const float* w2 = (const float*)d_in[7];
    const float* b2 = (const float*)d_in[8];
    const float* w3 = (const float*)d_in[9];
    const float* b3 = (const float*)d_in[10];
    float* out = (float*)d_out;

    cudaFuncSetAttribute(kB, cudaFuncAttributeMaxDynamicSharedMemorySize, C*TP*4);

    kA<<<8, 256>>>(vw, vb, w3);
    dim3 gB(H, NCH, B);
    kB<<<gB, 256, C*TP*4>>>(x, kw);
    kC<<<B, 256>>>(vw, vb, w1, b1, w2, b2);
    kD<<<(B*HW)/256, 256>>>(b3);
    kE<<<(B*C*HW/4)/256, 256>>>((const float4*)x, (float4*)out);
}

// round 3
// speedup vs baseline: 1.9341x; 1.3101x over previous
#include <cuda_runtime.h>
#include <cuda_bf16.h>
#include <math_constants.h>

// x = [B=8, C=256, H=128, W=128] fp32
#define B 8
#define C 256
#define H 128
#define W 128
#define HW (H*W)
#define WC 32             // w-chunk per kB block
#define NCH 4             // W / WC
#define TP4 9             // tile pitch in float4 (36 floats/row)

// ---------- scratch ----------
__device__ float g_u[C];
__device__ float g_ub;
__device__ __align__(16) float g_t3[B*HW];
__device__ __align__(16) float g_xkpart[B*H*NCH*C];   // [b][h][chunk][c]
__device__ float g_Zp[B*H*NCH];
__device__ float g_cmax[B*H*W];
__device__ float g_csum[B*H*W];
__device__ float g_hmaxp[B*H*NCH];
__device__ float g_hsump[B*H*NCH];
__device__ float g_hatt[B*H];
__device__ float g_watt[B*W];
__device__ float g_cf[B*C];
__device__ __align__(16) float g_s[B*HW];

// ---------- kA: u = w3^T v_w, ub = w3.v_b ----------
__global__ void __launch_bounds__(256) kA(const float* __restrict__ vw,
                                          const float* __restrict__ vb,
                                          const float* __restrict__ w3) {
    __shared__ float red[256];
    int t = threadIdx.x, lane = t & 31, g = t >> 5;
    int c = (blockIdx.x << 5) + lane;
    float u = 0.f;
    #pragma unroll
    for (int o = g; o < C; o += 8) u = fmaf(w3[o], vw[o*C + c], u);
    red[t] = u;
    __syncthreads();
    if (t < 32) {
        float s = 0.f;
        #pragma unroll
        for (int k2 = 0; k2 < 8; k2++) s += red[(k2 << 5) + t];
        g_u[(blockIdx.x << 5) + t] = s;
    }
    if (blockIdx.x == 0) {
        __syncthreads();
        red[t] = w3[t] * vb[t];
        __syncthreads();
        if (t < 32) {
            float s = 0.f;
            #pragma unroll
            for (int k2 = 0; k2 < 8; k2++) s += red[(k2 << 5) + t];
            #pragma unroll
            for (int o = 16; o; o >>= 1) s += __shfl_down_sync(0xffffffffu, s, o);
            if (t == 0) g_ub = s;
        }
    }
}

// ---------- kB: main reduction pass (float4, 5 CTAs/SM) ----------
// Block = (b, h, chunk of 32 w). Thread t: wid=t>>5, lane=t&31,
// cloc=lane>>3 (0..3), w4=lane&7 (float4 col). Channels: wid*32+cloc*8+j, j<8.
__global__ void __launch_bounds__(256, 5) kB(const float* __restrict__ x,
                                             const float* __restrict__ kw) {
    __shared__ float4 tile4[C*TP4];             // 36864 B, SW-free layout
    __shared__ float wsh[C], ush[C];
    __shared__ float red[4*256];                // [qty][warp*32 + w]
    __shared__ float esh[WC];

    int t = threadIdx.x, lane = t & 31, wid = t >> 5;
    int h = blockIdx.x, chunk = blockIdx.y, b = blockIdx.z;
    wsh[t] = kw[t];
    ush[t] = g_u[t];
    __syncthreads();

    int cloc = lane >> 3, w4 = lane & 7;
    int c0 = (wid << 5) + (cloc << 3);          // first of 8 channels
    const float4* xp = (const float4*)(x + (((size_t)(b*C + c0)) << 14)
                                         + (h << 7) + (chunk << 5)) + w4;

    float kl[4] = {0,0,0,0}, t3[4] = {0,0,0,0}, sm[4] = {0,0,0,0};
    float mx[4] = {-1e30f,-1e30f,-1e30f,-1e30f};
    #pragma unroll
    for (int j = 0; j < 8; j++) {
        float4 v = __ldcs(xp + ((size_t)j << 12));   // +j*HW/4
        int c = c0 + j;
        tile4[c*TP4 + w4] = v;
        float kc = wsh[c], uc = ush[c];
        kl[0]=fmaf(kc,v.x,kl[0]); kl[1]=fmaf(kc,v.y,kl[1]); kl[2]=fmaf(kc,v.z,kl[2]); kl[3]=fmaf(kc,v.w,kl[3]);
        t3[0]=fmaf(uc,v.x,t3[0]); t3[1]=fmaf(uc,v.y,t3[1]); t3[2]=fmaf(uc,v.z,t3[2]); t3[3]=fmaf(uc,v.w,t3[3]);
        mx[0]=fmaxf(mx[0],v.x); mx[1]=fmaxf(mx[1],v.y); mx[2]=fmaxf(mx[2],v.z); mx[3]=fmaxf(mx[3],v.w);
        sm[0]+=v.x; sm[1]+=v.y; sm[2]+=v.z; sm[3]+=v.w;
    }
    // in-warp reduce across cloc (lanes stride 8)
    #pragma unroll
    for (int o = 16; o >= 8; o >>= 1) {
        #pragma unroll
        for (int l = 0; l < 4; l++) {
            kl[l] += __shfl_down_sync(0xffffffffu, kl[l], o);
            t3[l] += __shfl_down_sync(0xffffffffu, t3[l], o);
            mx[l] = fmaxf(mx[l], __shfl_down_sync(0xffffffffu, mx[l], o));
            sm[l] += __shfl_down_sync(0xffffffffu, sm[l], o);
        }
    }
    if (lane < 8) {
        int base = (wid << 5) + (lane << 2);
        #pragma unroll
        for (int l = 0; l < 4; l++) {
            red[base + l]       = kl[l];
            red[256 + base + l] = t3[l];
            red[512 + base + l] = mx[l];
            red[768 + base + l] = sm[l];
        }
    }
    __syncthreads();

    int bh = (b << 7) + h;
    int ci = (bh << 2) + chunk;
    if (t < 32) {
        float klw = 0.f, t3w = 0.f, smw = 0.f, mxw = -1e30f;
        #pragma unroll
        for (int wp = 0; wp < 8; wp++) {
            klw += red[(wp << 5) + t];
            t3w += red[256 + (wp << 5) + t];
            mxw = fmaxf(mxw, red[512 + (wp << 5) + t]);
            smw += red[768 + (wp << 5) + t];
        }
        float e = __expf(klw);                    // klin ~ N(0,1): no shift needed
        esh[t] = e;
        int gi = (bh << 7) + (chunk << 5) + t;
        g_t3[gi]   = t3w + g_ub;
        g_cmax[gi] = mxw;
        g_csum[gi] = smw;
        float rm = mxw, rs = smw, rz = e;
        #pragma unroll
        for (int o = 16; o; o >>= 1) {
            rm = fmaxf(rm, __shfl_down_sync(0xffffffffu, rm, o));
            rs += __shfl_down_sync(0xffffffffu, rs, o);
            rz += __shfl_down_sync(0xffffffffu, rz, o);
        }
        if (t == 0) { g_hmaxp[ci] = rm; g_hsump[ci] = rs; g_Zp[ci] = rz; }
    }
    __syncthreads();

    // phase 2: xk partial; thread t = channel c, rotated walk (bank-safe)
    const float* row = (const float*)(tile4 + t*TP4);
    float acc = 0.f;
    #pragma unroll
    for (int wp = 0; wp < WC; wp++) {
        int w = (wp + 5*t) & 31;
        acc = fmaf(row[w], esh[w], acc);
    }
    g_xkpart[((size_t)ci << 8) + t] = acc;
}

// ---------- kC: per-batch fixups ----------
__global__ void __launch_bounds__(256) kC(const float* __restrict__ vw,
                                          const float* __restrict__ vb,
                                          const float* __restrict__ w1,
                                          const float* __restrict__ b1,
                                          const float* __restrict__ w2,
                                          const float* __restrict__ b2) {
    __shared__ float xksh[C];
    __shared__ float red2[4*C];
    __shared__ float zp[8];
    __shared__ float zsh;
    int b = blockIdx.x, t = threadIdx.x;
    int lane = t & 31, wid = t >> 5;

    float z = g_Zp[(b << 9) + t] + g_Zp[(b << 9) + 256 + t];
    #pragma unroll
    for (int o = 16; o; o >>= 1) z += __shfl_down_sync(0xffffffffu, z, o);
    if (lane == 0) zp[wid] = z;
    __syncthreads();
    if (t == 0) zsh = zp[0]+zp[1]+zp[2]+zp[3]+zp[4]+zp[5]+zp[6]+zp[7];

    // xk: 4 i-slices x 64 float4 channel lanes
    int slice = t >> 6, c4 = t & 63;
    const float4* xkp4 = (const float4*)g_xkpart;
    float4 a4 = make_float4(0.f,0.f,0.f,0.f);
    #pragma unroll 8
    for (int ii = 0; ii < 128; ii++) {
        int i = (slice << 7) + ii;
        float4 v = xkp4[((size_t)((b << 9) + i) << 6) + c4];
        a4.x += v.x; a4.y += v.y; a4.z += v.z; a4.w += v.w;
    }
    red2[slice*C + (c4 << 2) + 0] = a4.x;
    red2[slice*C + (c4 << 2) + 1] = a4.y;
    red2[slice*C + (c4 << 2) + 2] = a4.z;
    red2[slice*C + (c4 << 2) + 3] = a4.w;
    __syncthreads();
    float invZ = 1.f / zsh;
    xksh[t] = (red2[t] + red2[C + t] + red2[2*C + t] + red2[3*C + t]) * invZ;
    __syncthreads();

    // cf = v_w @ xk + v_b (warp-per-row, float4)
    const float4* vw4 = (const float4*)vw;
    const float4* xk4 = (const float4*)xksh;
    for (int o = wid; o < C; o += 8) {
        float a = 0.f;
        #pragma unroll
        for (int k2 = 0; k2 < 2; k2++) {
            int idx = (k2 << 5) + lane;
            float4 wv = vw4[(o << 6) + idx];
            float4 xv = xk4[idx];
            a = fmaf(wv.x, xv.x, fmaf(wv.y, xv.y, fmaf(wv.z, xv.z, fmaf(wv.w, xv.w, a))));
        }
        #pragma unroll
        for (int o2 = 16; o2; o2 >>= 1) a += __shfl_down_sync(0xffffffffu, a, o2);
        if (lane == 0) g_cf[(b << 8) + o] = a + vb[o];
    }

    if (t < 128) {
        int i4 = ((b << 7) + t) << 2;
        float hm = fmaxf(fmaxf(g_hmaxp[i4], g_hmaxp[i4+1]),
                         fmaxf(g_hmaxp[i4+2], g_hmaxp[i4+3]));
        float hs = g_hsump[i4] + g_hsump[i4+1] + g_hsump[i4+2] + g_hsump[i4+3];
        float ha = fmaf(w1[0], hm, fmaf(w1[1], hs * (1.f/32768.f), b1[0]));
        g_hatt[(b << 7) + t] = 1.f / (1.f + __expf(-ha));

        float wm = -1e30f, ws = 0.f;
        #pragma unroll 4
        for (int hh = 0; hh < 128; hh++) {
            int idx = (((b << 7) + hh) << 7) + t;
            wm = fmaxf(wm, g_cmax[idx]);
            ws += g_csum[idx];
        }
        float wa = fmaf(w2[0], wm, fmaf(w2[1], ws * (1.f/32768.f), b2[0]));
        g_watt[(b << 7) + t] = 1.f / (1.f + __expf(-wa));
    }
}

// ---------- kD: spatial gate ----------
__global__ void __launch_bounds__(256) kD(const float* __restrict__ b3) {
    int i = blockIdx.x * 256 + threadIdx.x;
    int b = i >> 14, n = i & 16383;
    float att = g_hatt[(b << 7) + (n >> 7)] + g_watt[(b << 7) + (n & 127)];
    float zz = fmaf(att, g_t3[i], b3[0]);
    g_s[i] = 1.f / (1.f + __expf(-zz));
}

// ---------- kE: out = s*cf + x ----------
__global__ void __launch_bounds__(256) kE(const float4* __restrict__ x4,
                                          float4* __restrict__ o4) {
    int i = blockIdx.x * 256 + threadIdx.x;
    float4 xv = __ldcs(x4 + i);
    int b  = i >> 20;
    int c  = (i >> 12) & 255;
    int n4 = i & 4095;
    float4 sv = reinterpret_cast<const float4*>(g_s)[(b << 12) + n4];
    float cf  = g_cf[(b << 8) + c];
    float4 ov;
    ov.x = fmaf(sv.x, cf, xv.x);
    ov.y = fmaf(sv.y, cf, xv.y);
    ov.z = fmaf(sv.z, cf, xv.z);
    ov.w = fmaf(sv.w, cf, xv.w);
    __stcs(o4 + i, ov);
}

extern "C" void kernel_launch(void* const* d_in, const int* in_sizes, int n_in,
                              void* d_out, int out_size) {
    const float* x  = (const float*)d_in[0];
    const float* vw = (const float*)d_in[1];
    const float* vb = (const float*)d_in[2];
    const float* kw = (const float*)d_in[3];
    // d_in[4] = k_b: softmax shift-invariant, unused
    const float* w1 = (const float*)d_in[5];
    const float* b1 = (const float*)d_in[6];
    const float* w2 = (const float*)d_in[7];
    const float* b2 = (const float*)d_in[8];
    const float* w3 = (const float*)d_in[9];
    const float* b3 = (const float*)d_in[10];
    float* out = (float*)d_out;

    kA<<<8, 256>>>(vw, vb, w3);
    dim3 gB(H, NCH, B);
    kB<<<gB, 256>>>(x, kw);
    kC<<<B, 256>>>(vw, vb, w1, b1, w2, b2);
    kD<<<(B*HW)/256, 256>>>(b3);
    kE<<<(B*C*HW/4)/256, 256>>>((const float4*)x, (float4*)out);
}

// round 4
// speedup vs baseline: 1.9997x; 1.0339x over previous
#include <cuda_runtime.h>
#include <cuda_bf16.h>
#include <math_constants.h>

// x = [B=8, C=256, H=128, W=128] fp32
#define B 8
#define C 256
#define H 128
#define W 128
#define HW (H*W)
#define WC 32             // w-chunk per kB block
#define NCH 4             // W / WC
#define TP4 9             // tile pitch in float4 (36 floats/row)

// ---------- scratch ----------
__device__ float g_u[C];
__device__ float g_ub;
__device__ __align__(16) float g_t3[B*HW];
__device__ __align__(16) float g_xkpart[B*H*NCH*C];   // [b][h][chunk][c]
__device__ float g_Zp[B*H*NCH];
__device__ float g_cmax[B*H*W];
__device__ float g_csum[B*H*W];
__device__ float g_hmaxp[B*H*NCH];
__device__ float g_hsump[B*H*NCH];
__device__ float g_hatt[B*H];
__device__ float g_watt[B*W];
__device__ float g_cf[B*C];
__device__ __align__(16) float g_s[B*HW];

// ---------- kA: u = w3^T v_w, ub = w3.v_b ----------
__global__ void __launch_bounds__(256) kA(const float* __restrict__ vw,
                                          const float* __restrict__ vb,
                                          const float* __restrict__ w3) {
    __shared__ float red[256];
    int t = threadIdx.x, lane = t & 31, g = t >> 5;
    int c = (blockIdx.x << 5) + lane;
    float u = 0.f;
    #pragma unroll
    for (int o = g; o < C; o += 8) u = fmaf(w3[o], vw[o*C + c], u);
    red[t] = u;
    __syncthreads();
    if (t < 32) {
        float s = 0.f;
        #pragma unroll
        for (int k2 = 0; k2 < 8; k2++) s += red[(k2 << 5) + t];
        g_u[(blockIdx.x << 5) + t] = s;
    }
    if (blockIdx.x == 0) {
        __syncthreads();
        red[t] = w3[t] * vb[t];
        __syncthreads();
        if (t < 32) {
            float s = 0.f;
            #pragma unroll
            for (int k2 = 0; k2 < 8; k2++) s += red[(k2 << 5) + t];
            #pragma unroll
            for (int o = 16; o; o >>= 1) s += __shfl_down_sync(0xffffffffu, s, o);
            if (t == 0) g_ub = s;
        }
    }
}

// ---------- kB: main reduction pass (float4, 4 CTAs/SM, 64 regs) ----------
// Block = (b, h, chunk of 32 w). Thread t: wid=t>>5, lane=t&31,
// cloc=lane>>3 (0..3), w4=lane&7 (float4 col). Channels: wid*32+cloc*8+j, j<8.
__global__ void __launch_bounds__(256, 4) kB(const float* __restrict__ x,
                                             const float* __restrict__ kw) {
    __shared__ float4 tile4[C*TP4];             // 36864 B
    __shared__ float wsh[C], ush[C];
    __shared__ float red[4*256];                // [qty][warp*32 + w]
    __shared__ float esh[WC];

    int t = threadIdx.x, lane = t & 31, wid = t >> 5;
    int h = blockIdx.x, chunk = blockIdx.y, b = blockIdx.z;
    wsh[t] = kw[t];
    ush[t] = g_u[t];
    __syncthreads();

    int cloc = lane >> 3, w4 = lane & 7;
    int c0 = (wid << 5) + (cloc << 3);          // first of 8 channels
    const float4* xp = (const float4*)(x + (((size_t)(b*C + c0)) << 14)
                                         + (h << 7) + (chunk << 5)) + w4;

    // batch all 8 loads first: MLP = 8 per thread
    float4 v[8];
    #pragma unroll
    for (int j = 0; j < 8; j++) v[j] = __ldcs(xp + ((size_t)j << 12));  // +j*HW/4

    float kl[4] = {0,0,0,0}, t3[4] = {0,0,0,0}, sm[4] = {0,0,0,0};
    float mx[4] = {-1e30f,-1e30f,-1e30f,-1e30f};
    #pragma unroll
    for (int j = 0; j < 8; j++) {
        int c = c0 + j;
        tile4[c*TP4 + w4] = v[j];
        float kc = wsh[c], uc = ush[c];
        kl[0]=fmaf(kc,v[j].x,kl[0]); kl[1]=fmaf(kc,v[j].y,kl[1]); kl[2]=fmaf(kc,v[j].z,kl[2]); kl[3]=fmaf(kc,v[j].w,kl[3]);
        t3[0]=fmaf(uc,v[j].x,t3[0]); t3[1]=fmaf(uc,v[j].y,t3[1]); t3[2]=fmaf(uc,v[j].z,t3[2]); t3[3]=fmaf(uc,v[j].w,t3[3]);
        mx[0]=fmaxf(mx[0],v[j].x); mx[1]=fmaxf(mx[1],v[j].y); mx[2]=fmaxf(mx[2],v[j].z); mx[3]=fmaxf(mx[3],v[j].w);
        sm[0]+=v[j].x; sm[1]+=v[j].y; sm[2]+=v[j].z; sm[3]+=v[j].w;
    }
    // in-warp reduce across cloc (lanes stride 8)
    #pragma unroll
    for (int o = 16; o >= 8; o >>= 1) {
        #pragma unroll
        for (int l = 0; l < 4; l++) {
            kl[l] += __shfl_down_sync(0xffffffffu, kl[l], o);
            t3[l] += __shfl_down_sync(0xffffffffu, t3[l], o);
            mx[l] = fmaxf(mx[l], __shfl_down_sync(0xffffffffu, mx[l], o));
            sm[l] += __shfl_down_sync(0xffffffffu, sm[l], o);
        }
    }
    if (lane < 8) {
        int base = (wid << 5) + (lane << 2);
        #pragma unroll
        for (int l = 0; l < 4; l++) {
            red[base + l]       = kl[l];
            red[256 + base + l] = t3[l];
            red[512 + base + l] = mx[l];
            red[768 + base + l] = sm[l];
        }
    }
    __syncthreads();

    int bh = (b << 7) + h;
    int ci = (bh << 2) + chunk;
    if (t < 32) {
        float klw = 0.f, t3w = 0.f, smw = 0.f, mxw = -1e30f;
        #pragma unroll
        for (int wp = 0; wp < 8; wp++) {
            klw += red[(wp << 5) + t];
            t3w += red[256 + (wp << 5) + t];
            mxw = fmaxf(mxw, red[512 + (wp << 5) + t]);
            smw += red[768 + (wp << 5) + t];
        }
        float e = __expf(klw);                    // klin ~ N(0,1): no shift needed
        esh[t] = e;
        int gi = (bh << 7) + (chunk << 5) + t;
        g_t3[gi]   = t3w + g_ub;
        g_cmax[gi] = mxw;
        g_csum[gi] = smw;
        float rm = mxw, rs = smw, rz = e;
        #pragma unroll
        for (int o = 16; o; o >>= 1) {
            rm = fmaxf(rm, __shfl_down_sync(0xffffffffu, rm, o));
            rs += __shfl_down_sync(0xffffffffu, rs, o);
            rz += __shfl_down_sync(0xffffffffu, rz, o);
        }
        if (t == 0) { g_hmaxp[ci] = rm; g_hsump[ci] = rs; g_Zp[ci] = rz; }
    }
    __syncthreads();

    // phase 2: xk partial; thread t = channel c, rotated walk (bank-safe:
    // bank = (9t + wp) mod 32, bijection in t since 9 is odd)
    const float* row = (const float*)(tile4 + t*TP4);
    float acc = 0.f;
    #pragma unroll
    for (int wp = 0; wp < WC; wp++) {
        int w = (wp + 5*t) & 31;
        acc = fmaf(row[w], esh[w], acc);
    }
    g_xkpart[((size_t)ci << 8) + t] = acc;
}

// ---------- kC: per-batch fixups ----------
__global__ void __launch_bounds__(256) kC(const float* __restrict__ vw,
                                          const float* __restrict__ vb,
                                          const float* __restrict__ w1,
                                          const float* __restrict__ b1,
                                          const float* __restrict__ w2,
                                          const float* __restrict__ b2) {
    __shared__ float xksh[C];
    __shared__ float red2[4*C];
    __shared__ float zp[8];
    __shared__ float zsh;
    int b = blockIdx.x, t = threadIdx.x;
    int lane = t & 31, wid = t >> 5;

    float z = g_Zp[(b << 9) + t] + g_Zp[(b << 9) + 256 + t];
    #pragma unroll
    for (int o = 16; o; o >>= 1) z += __shfl_down_sync(0xffffffffu, z, o);
    if (lane == 0) zp[wid] = z;
    __syncthreads();
    if (t == 0) zsh = zp[0]+zp[1]+zp[2]+zp[3]+zp[4]+zp[5]+zp[6]+zp[7];

    // xk: 4 i-slices x 64 float4 channel lanes
    int slice = t >> 6, c4 = t & 63;
    const float4* xkp4 = (const float4*)g_xkpart;
    float4 a4 = make_float4(0.f,0.f,0.f,0.f);
    #pragma unroll 8
    for (int ii = 0; ii < 128; ii++) {
        int i = (slice << 7) + ii;
        float4 v = xkp4[((size_t)((b << 9) + i) << 6) + c4];
        a4.x += v.x; a4.y += v.y; a4.z += v.z; a4.w += v.w;
    }
    red2[slice*C + (c4 << 2) + 0] = a4.x;
    red2[slice*C + (c4 << 2) + 1] = a4.y;
    red2[slice*C + (c4 << 2) + 2] = a4.z;
    red2[slice*C + (c4 << 2) + 3] = a4.w;
    __syncthreads();
    float invZ = 1.f / zsh;
    xksh[t] = (red2[t] + red2[C + t] + red2[2*C + t] + red2[3*C + t]) * invZ;
    __syncthreads();

    // cf = v_w @ xk + v_b (warp-per-row, float4)
    const float4* vw4 = (const float4*)vw;
    const float4* xk4 = (const float4*)xksh;
    for (int o = wid; o < C; o += 8) {
        float a = 0.f;
        #pragma unroll
        for (int k2 = 0; k2 < 2; k2++) {
            int idx = (k2 << 5) + lane;
            float4 wv = vw4[(o << 6) + idx];
            float4 xv = xk4[idx];
            a = fmaf(wv.x, xv.x, fmaf(wv.y, xv.y, fmaf(wv.z, xv.z, fmaf(wv.w, xv.w, a))));
        }
        #pragma unroll
        for (int o2 = 16; o2; o2 >>= 1) a += __shfl_down_sync(0xffffffffu, a, o2);
        if (lane == 0) g_cf[(b << 8) + o] = a + vb[o];
    }

    if (t < 128) {
        int i4 = ((b << 7) + t) << 2;
        float hm = fmaxf(fmaxf(g_hmaxp[i4], g_hmaxp[i4+1]),
                         fmaxf(g_hmaxp[i4+2], g_hmaxp[i4+3]));
        float hs = g_hsump[i4] + g_hsump[i4+1] + g_hsump[i4+2] + g_hsump[i4+3];
        float ha = fmaf(w1[0], hm, fmaf(w1[1], hs * (1.f/32768.f), b1[0]));
        g_hatt[(b << 7) + t] = 1.f / (1.f + __expf(-ha));

        float wm = -1e30f, ws = 0.f;
        #pragma unroll 4
        for (int hh = 0; hh < 128; hh++) {
            int idx = (((b << 7) + hh) << 7) + t;
            wm = fmaxf(wm, g_cmax[idx]);
            ws += g_csum[idx];
        }
        float wa = fmaf(w2[0], wm, fmaf(w2[1], ws * (1.f/32768.f), b2[0]));
        g_watt[(b << 7) + t] = 1.f / (1.f + __expf(-wa));
    }
}

// ---------- kD: spatial gate ----------
__global__ void __launch_bounds__(256) kD(const float* __restrict__ b3) {
    int i = blockIdx.x * 256 + threadIdx.x;
    int b = i >> 14, n = i & 16383;
    float att = g_hatt[(b << 7) + (n >> 7)] + g_watt[(b << 7) + (n & 127)];
    float zz = fmaf(att, g_t3[i], b3[0]);
    g_s[i] = 1.f / (1.f + __expf(-zz));
}

// ---------- kE: out = s*cf + x ----------
__global__ void __launch_bounds__(256) kE(const float4* __restrict__ x4,
                                          float4* __restrict__ o4) {
    int i = blockIdx.x * 256 + threadIdx.x;
    float4 xv = __ldcs(x4 + i);
    int b  = i >> 20;
    int c  = (i >> 12) & 255;
    int n4 = i & 4095;
    float4 sv = reinterpret_cast<const float4*>(g_s)[(b << 12) + n4];
    float cf  = g_cf[(b << 8) + c];
    float4 ov;
    ov.x = fmaf(sv.x, cf, xv.x);
    ov.y = fmaf(sv.y, cf, xv.y);
    ov.z = fmaf(sv.z, cf, xv.z);
    ov.w = fmaf(sv.w, cf, xv.w);
    __stcs(o4 + i, ov);
}

extern "C" void kernel_launch(void* const* d_in, const int* in_sizes, int n_in,
                              void* d_out, int out_size) {
    const float* x  = (const float*)d_in[0];
    const float* vw = (const float*)d_in[1];
    const float* vb = (const float*)d_in[2];
    const float* kw = (const float*)d_in[3];
    // d_in[4] = k_b: softmax shift-invariant, unused
    const float* w1 = (const float*)d_in[5];
    const float* b1 = (const float*)d_in[6];
    const float* w2 = (const float*)d_in[7];
    const float* b2 = (const float*)d_in[8];
    const float* w3 = (const float*)d_in[9];
    const float* b3 = (const float*)d_in[10];
    float* out = (float*)d_out;

    kA<<<8, 256>>>(vw, vb, w3);
    dim3 gB(H, NCH, B);
    kB<<<gB, 256>>>(x, kw);
    kC<<<B, 256>>>(vw, vb, w1, b1, w2, b2);
    kD<<<(B*HW)/256, 256>>>(b3);
    kE<<<(B*C*HW/4)/256, 256>>>((const float4*)x, (float4*)out);
}